// round 1
// baseline (speedup 1.0000x reference)
#include <cuda_runtime.h>
#include <cstddef>

#define Bdim 4
#define Tdim 2048
#define Cdim 1024
#define Hdim 16
#define Ddim 64
#define C3   3072
#define Mrows (Bdim * Tdim)   // 8192

// Scratch: qkv [8192, 3072] and attention output [8192, 1024] (fp32)
__device__ float g_qkv[(size_t)Mrows * C3];
__device__ float g_att[(size_t)Mrows * Cdim];

// ---------------------------------------------------------------------------
// GEMM: C[M,N] = A[M,K] @ B[K,N] + bias[N]
// 128x128x16 tile, 256 threads, 8x8 per-thread microtile. All dims divisible.
// ---------------------------------------------------------------------------
__global__ __launch_bounds__(256) void gemm_bias_kernel(
    const float* __restrict__ A, const float* __restrict__ B,
    const float* __restrict__ bias, float* __restrict__ C,
    int M, int N, int K)
{
    __shared__ float As[16][132];   // transposed A tile, padded vs bank conflicts
    __shared__ float Bs[16][128];

    const int tid = threadIdx.x;
    const int bm = blockIdx.y * 128;
    const int bn = blockIdx.x * 128;
    const int tx = tid & 15;        // 16 col groups
    const int ty = tid >> 4;        // 16 row groups

    float acc[8][8];
#pragma unroll
    for (int i = 0; i < 8; i++)
#pragma unroll
        for (int j = 0; j < 8; j++) acc[i][j] = 0.0f;

    const float* Aptr = A + (size_t)bm * K;
    const float* Bptr = B + bn;

    for (int k0 = 0; k0 < K; k0 += 16) {
        // Load A tile 128x16 (512 float4, 2 per thread), store transposed
#pragma unroll
        for (int i = 0; i < 2; i++) {
            int lin = tid + i * 256;          // 0..511
            int row = lin >> 2;               // 0..127
            int c4  = lin & 3;                // 0..3
            float4 v = *reinterpret_cast<const float4*>(
                Aptr + (size_t)row * K + k0 + c4 * 4);
            As[c4 * 4 + 0][row] = v.x;
            As[c4 * 4 + 1][row] = v.y;
            As[c4 * 4 + 2][row] = v.z;
            As[c4 * 4 + 3][row] = v.w;
        }
        // Load B tile 16x128 (512 float4, 2 per thread)
#pragma unroll
        for (int i = 0; i < 2; i++) {
            int lin = tid + i * 256;
            int row = lin >> 5;               // 0..15
            int c4  = lin & 31;               // 0..31
            *reinterpret_cast<float4*>(&Bs[row][c4 * 4]) =
                *reinterpret_cast<const float4*>(Bptr + (size_t)(k0 + row) * N + c4 * 4);
        }
        __syncthreads();

#pragma unroll
        for (int kk = 0; kk < 16; kk++) {
            float a[8], b[8];
            {
                float4 a0 = *reinterpret_cast<const float4*>(&As[kk][ty * 8]);
                float4 a1 = *reinterpret_cast<const float4*>(&As[kk][ty * 8 + 4]);
                a[0]=a0.x; a[1]=a0.y; a[2]=a0.z; a[3]=a0.w;
                a[4]=a1.x; a[5]=a1.y; a[6]=a1.z; a[7]=a1.w;
                float4 b0 = *reinterpret_cast<const float4*>(&Bs[kk][tx * 8]);
                float4 b1 = *reinterpret_cast<const float4*>(&Bs[kk][tx * 8 + 4]);
                b[0]=b0.x; b[1]=b0.y; b[2]=b0.z; b[3]=b0.w;
                b[4]=b1.x; b[5]=b1.y; b[6]=b1.z; b[7]=b1.w;
            }
#pragma unroll
            for (int i = 0; i < 8; i++)
#pragma unroll
                for (int j = 0; j < 8; j++)
                    acc[i][j] = fmaf(a[i], b[j], acc[i][j]);
        }
        __syncthreads();
    }

#pragma unroll
    for (int i = 0; i < 8; i++) {
        int row = bm + ty * 8 + i;
#pragma unroll
        for (int j = 0; j < 8; j += 4) {
            int col = bn + tx * 8 + j;
            float4 o;
            o.x = acc[i][j + 0] + bias[col + 0];
            o.y = acc[i][j + 1] + bias[col + 1];
            o.z = acc[i][j + 2] + bias[col + 2];
            o.w = acc[i][j + 3] + bias[col + 3];
            *reinterpret_cast<float4*>(C + (size_t)row * N + col) = o;
        }
    }
}

// ---------------------------------------------------------------------------
// Causal flash attention, fp32. One thread owns one query row.
// qkv layout: [b*T+t][3072] with q=[0,1024), k=[1024,2048), v=[2048,3072).
// Output written in [B,T,C] layout (== transpose(0,2,1,3).reshape).
// Grid: (T/128, B*H), 128 threads.
// ---------------------------------------------------------------------------
__global__ __launch_bounds__(128) void attn_kernel(
    const float* __restrict__ qkv, float* __restrict__ out)
{
    __shared__ float Ks[64][64];
    __shared__ float Vs[64][64];

    const int bh  = blockIdx.y;
    const int b   = bh >> 4;
    const int h   = bh & 15;
    const int tid = threadIdx.x;
    const int qi  = blockIdx.x * 128 + tid;   // this thread's query index
    const float scale = 0.125f;               // 1/sqrt(64)

    // Load this thread's q row into registers
    float q[64];
    {
        const float* qrow = qkv + ((size_t)(b * Tdim + qi)) * C3 + h * Ddim;
#pragma unroll
        for (int d4 = 0; d4 < 16; d4++) {
            float4 v = *reinterpret_cast<const float4*>(qrow + d4 * 4);
            q[d4*4+0] = v.x; q[d4*4+1] = v.y; q[d4*4+2] = v.z; q[d4*4+3] = v.w;
        }
    }

    float m = -1e30f, l = 0.0f;
    float o[64];
#pragma unroll
    for (int d = 0; d < 64; d++) o[d] = 0.0f;

    const int nkb = blockIdx.x * 2 + 2;       // key tiles of 64 covering [0, qb*128+128)
    for (int jb = 0; jb < nkb; jb++) {
        // Cooperative load of K,V tiles [64][64]
        const float* Kbase = qkv + ((size_t)(b * Tdim + jb * 64)) * C3 + Cdim  + h * Ddim;
        const float* Vbase = Kbase + Cdim;
#pragma unroll
        for (int i = 0; i < 8; i++) {
            int lin = tid + i * 128;          // 0..1023 float4 slots
            int row = lin >> 4;               // 0..63
            int c4  = lin & 15;               // 0..15
            *reinterpret_cast<float4*>(&Ks[row][c4 * 4]) =
                *reinterpret_cast<const float4*>(Kbase + (size_t)row * C3 + c4 * 4);
            *reinterpret_cast<float4*>(&Vs[row][c4 * 4]) =
                *reinterpret_cast<const float4*>(Vbase + (size_t)row * C3 + c4 * 4);
        }
        __syncthreads();

        int jmax = qi - jb * 64 + 1;          // causal: keys <= qi
        if (jmax > 64) jmax = 64;
        for (int jj = 0; jj < jmax; jj++) {
            float s = 0.0f;
            const float4* krow = reinterpret_cast<const float4*>(&Ks[jj][0]);
#pragma unroll
            for (int d4 = 0; d4 < 16; d4++) {
                float4 kv = krow[d4];
                s = fmaf(q[d4*4+0], kv.x, s);
                s = fmaf(q[d4*4+1], kv.y, s);
                s = fmaf(q[d4*4+2], kv.z, s);
                s = fmaf(q[d4*4+3], kv.w, s);
            }
            s *= scale;

            if (s > m) {                       // rare after warm-up: amortized rescale
                float alpha = __expf(m - s);
                l *= alpha;
#pragma unroll
                for (int d = 0; d < 64; d++) o[d] *= alpha;
                m = s;
            }
            float p = __expf(s - m);
            l += p;
            const float4* vrow = reinterpret_cast<const float4*>(&Vs[jj][0]);
#pragma unroll
            for (int d4 = 0; d4 < 16; d4++) {
                float4 vv = vrow[d4];
                o[d4*4+0] = fmaf(p, vv.x, o[d4*4+0]);
                o[d4*4+1] = fmaf(p, vv.y, o[d4*4+1]);
                o[d4*4+2] = fmaf(p, vv.z, o[d4*4+2]);
                o[d4*4+3] = fmaf(p, vv.w, o[d4*4+3]);
            }
        }
        __syncthreads();
    }

    float inv = 1.0f / l;
    float* orow = out + ((size_t)(b * Tdim + qi)) * Cdim + h * Ddim;
#pragma unroll
    for (int d4 = 0; d4 < 16; d4++) {
        float4 v;
        v.x = o[d4*4+0] * inv; v.y = o[d4*4+1] * inv;
        v.z = o[d4*4+2] * inv; v.w = o[d4*4+3] * inv;
        *reinterpret_cast<float4*>(orow + d4 * 4) = v;
    }
}

// ---------------------------------------------------------------------------
extern "C" void kernel_launch(void* const* d_in, const int* in_sizes, int n_in,
                              void* d_out, int out_size)
{
    (void)in_sizes; (void)n_in; (void)out_size;
    const float* x      = (const float*)d_in[0];
    const float* W_attn = (const float*)d_in[1];
    const float* b_attn = (const float*)d_in[2];
    const float* W_proj = (const float*)d_in[3];
    const float* b_proj = (const float*)d_in[4];
    float* out = (float*)d_out;

    float* qkv = nullptr;
    float* att = nullptr;
    cudaGetSymbolAddress((void**)&qkv, g_qkv);
    cudaGetSymbolAddress((void**)&att, g_att);

    // 1) QKV = x @ W_attn + b_attn
    {
        dim3 grid(C3 / 128, Mrows / 128);
        gemm_bias_kernel<<<grid, 256>>>(x, W_attn, b_attn, qkv, Mrows, C3, Cdim);
    }
    // 2) Causal flash attention -> att in [B,T,C]
    {
        dim3 grid(Tdim / 128, Bdim * Hdim);
        attn_kernel<<<grid, 128>>>(qkv, att);
    }
    // 3) out = att @ W_proj + b_proj
    {
        dim3 grid(Cdim / 128, Mrows / 128);
        gemm_bias_kernel<<<grid, 256>>>(att, W_proj, b_proj, out, Mrows, Cdim, Cdim);
    }
}